// round 2
// baseline (speedup 1.0000x reference)
#include <cuda_runtime.h>

#define NI 64

__global__ __launch_bounds__(256) void henon_kernel(
    const float4* __restrict__ z,
    const float*  __restrict__ W_in,   // (2, 64) row-major
    const float*  __restrict__ W_out,  // (64, 1)
    const float*  __restrict__ b_in,   // (1, 64)
    const float*  __restrict__ eta,    // (1, 2)
    float4* __restrict__ out,
    int nrows)
{
    // Packed per-neuron constants, broadcast-read by all lanes.
    __shared__ float4 wpk[NI];  // {W_in[0][i], W_in[1][i], b[i], 0}
    __shared__ float2 cpk[NI];  // {W_out[i]*W_in[0][i], W_out[i]*W_in[1][i]}

    int t = threadIdx.x;
    if (t < NI) {
        float w0 = W_in[t];        // W_in[0][t]
        float w1 = W_in[NI + t];   // W_in[1][t]
        float wo = W_out[t];
        wpk[t] = make_float4(w0, w1, b_in[t], 0.0f);
        cpk[t] = make_float2(wo * w0, wo * w1);
    }
    float e0 = __ldg(&eta[0]);
    float e1 = __ldg(&eta[1]);
    __syncthreads();

    int idx = blockIdx.x * blockDim.x + t;
    if (idx >= nrows) return;

    float4 zv = z[idx];
    float X0 = zv.x, X1 = zv.y, Y0 = zv.z, Y1 = zv.w;

    #pragma unroll 1
    for (int it = 0; it < 4; ++it) {
        float g0 = 0.0f, g1 = 0.0f;
        #pragma unroll
        for (int i = 0; i < NI; ++i) {
            float4 w = wpk[i];
            float a = fmaf(Y0, w.x, fmaf(Y1, w.y, w.z));
            float th;
            asm("tanh.approx.f32 %0, %1;" : "=f"(th) : "f"(a));
            float s = fmaf(-th, th, 1.0f);     // 1 - tanh^2
            float2 c = cpk[i];
            g0 = fmaf(s, c.x, g0);
            g1 = fmaf(s, c.y, g1);
        }
        // X' = Y + eta ; Y' = -X + eps*grad, eps = 1
        float nX0 = Y0 + e0;
        float nX1 = Y1 + e1;
        float nY0 = g0 - X0;
        float nY1 = g1 - X1;
        X0 = nX0; X1 = nX1; Y0 = nY0; Y1 = nY1;
    }

    out[idx] = make_float4(X0, X1, Y0, Y1);
}

extern "C" void kernel_launch(void* const* d_in, const int* in_sizes, int n_in,
                              void* d_out, int out_size)
{
    const float4* z     = (const float4*)d_in[0];
    const float*  W_in  = (const float*)d_in[1];
    const float*  W_out = (const float*)d_in[2];
    const float*  b_in  = (const float*)d_in[3];
    const float*  eta   = (const float*)d_in[4];
    int nrows = in_sizes[0] / 4;

    int threads = 256;
    int blocks = (nrows + threads - 1) / threads;
    henon_kernel<<<blocks, threads>>>(z, W_in, W_out, b_in, eta,
                                      (float4*)d_out, nrows);
}

// round 3
// speedup vs baseline: 4.0330x; 4.0330x over previous
#include <cuda_runtime.h>
#include <cstdint>

#define NI 64

typedef unsigned long long u64;

__device__ __forceinline__ u64 pk2(float lo, float hi) {
    u64 r;
    asm("mov.b64 %0, {%1, %2};" : "=l"(r) : "f"(lo), "f"(hi));
    return r;
}
__device__ __forceinline__ void upk2(u64 v, float& lo, float& hi) {
    asm("mov.b64 {%0, %1}, %2;" : "=f"(lo), "=f"(hi) : "l"(v));
}
__device__ __forceinline__ u64 fma2(u64 a, u64 b, u64 c) {
    u64 d;
    asm("fma.rn.f32x2 %0, %1, %2, %3;" : "=l"(d) : "l"(a), "l"(b), "l"(c));
    return d;
}
__device__ __forceinline__ u64 add2(u64 a, u64 b) {
    u64 d;
    asm("add.rn.f32x2 %0, %1, %2;" : "=l"(d) : "l"(a), "l"(b));
    return d;
}
__device__ __forceinline__ float tanhap(float x) {
    float r;
    asm("tanh.approx.f32 %0, %1;" : "=f"(r) : "f"(x));
    return r;
}

// Shared constants, pre-duplicated so broadcast LDS lands as packed f32x2:
//   wA[i] = {w0,w0, w1,w1}   (as ulonglong2: .x={w0,w0}, .y={w1,w1})
//   wB[i] = {b,b,   c0,c0}   c0 = W_out[i]*W_in[0][i]
//   wC[i] = {c1,c1}          c1 = W_out[i]*W_in[1][i]
__global__ __launch_bounds__(256, 3) void henon_kernel(
    const float4* __restrict__ z,
    const float*  __restrict__ W_in,
    const float*  __restrict__ W_out,
    const float*  __restrict__ b_in,
    const float*  __restrict__ eta,
    float4* __restrict__ out,
    int nrows)
{
    __shared__ float4 wA[NI];
    __shared__ float4 wB[NI];
    __shared__ float2 wC[NI];

    int t = threadIdx.x;
    if (t < NI) {
        float w0 = W_in[t];
        float w1 = W_in[NI + t];
        float wo = W_out[t];
        float b  = b_in[t];
        wA[t] = make_float4(w0, w0, w1, w1);
        wB[t] = make_float4(b, b, wo * w0, wo * w0);
        wC[t] = make_float2(wo * w1, wo * w1);
    }
    float e0 = __ldg(&eta[0]);
    float e1 = __ldg(&eta[1]);
    __syncthreads();

    int half = (nrows + 1) >> 1;
    int idx = blockIdx.x * blockDim.x + t;
    if (idx >= half) return;

    int idxB = idx + half;
    bool hasB = idxB < nrows;
    int idxBc = hasB ? idxB : idx;

    float4 za = z[idx];
    float4 zb = z[idxBc];

    // Packed state across the two rows (lo = row A, hi = row B)
    u64 pX0 = pk2(za.x, zb.x);
    u64 pX1 = pk2(za.y, zb.y);
    u64 pY0 = pk2(za.z, zb.z);
    u64 pY1 = pk2(za.w, zb.w);

    const u64 one2  = pk2(1.0f, 1.0f);
    const u64 neg2  = pk2(-1.0f, -1.0f);
    const u64 pe0   = pk2(e0, e0);
    const u64 pe1   = pk2(e1, e1);
    const u64 SGN   = 0x8000000080000000ull;

    const ulonglong2* wA64 = (const ulonglong2*)wA;
    const ulonglong2* wB64 = (const ulonglong2*)wB;
    const u64*        wC64 = (const u64*)wC;

    #pragma unroll 1
    for (int it = 0; it < 4; ++it) {
        u64 pg0 = 0ull;  // {0.0f, 0.0f}
        u64 pg1 = 0ull;
        #pragma unroll 4
        for (int i = 0; i < NI; ++i) {
            ulonglong2 a4 = wA64[i];          // {w0,w0},{w1,w1}
            ulonglong2 b4 = wB64[i];          // {b,b},{c0,c0}
            u64 c2        = wC64[i];          // {c1,c1}
            u64 pa = fma2(pY0, a4.x, fma2(pY1, a4.y, b4.x));
            float a0, a1;
            upk2(pa, a0, a1);
            u64 pt = pk2(tanhap(a0), tanhap(a1));
            u64 ps = fma2(pt ^ SGN, pt, one2);   // 1 - t*t
            pg0 = fma2(ps, b4.y, pg0);
            pg1 = fma2(ps, c2, pg1);
        }
        u64 nX0 = add2(pY0, pe0);
        u64 nX1 = add2(pY1, pe1);
        u64 nY0 = fma2(pX0, neg2, pg0);     // -X + grad (eps=1)
        u64 nY1 = fma2(pX1, neg2, pg1);
        pX0 = nX0; pX1 = nX1; pY0 = nY0; pY1 = nY1;
    }

    float xa0, xb0, xa1, xb1, ya0, yb0, ya1, yb1;
    upk2(pX0, xa0, xb0);
    upk2(pX1, xa1, xb1);
    upk2(pY0, ya0, yb0);
    upk2(pY1, ya1, yb1);

    out[idx] = make_float4(xa0, xa1, ya0, ya1);
    if (hasB)
        out[idxB] = make_float4(xb0, xb1, yb0, yb1);
}

extern "C" void kernel_launch(void* const* d_in, const int* in_sizes, int n_in,
                              void* d_out, int out_size)
{
    const float4* z     = (const float4*)d_in[0];
    const float*  W_in  = (const float*)d_in[1];
    const float*  W_out = (const float*)d_in[2];
    const float*  b_in  = (const float*)d_in[3];
    const float*  eta   = (const float*)d_in[4];
    int nrows = in_sizes[0] / 4;
    int half = (nrows + 1) / 2;

    int threads = 256;
    int blocks = (half + threads - 1) / threads;
    henon_kernel<<<blocks, threads>>>(z, W_in, W_out, b_in, eta,
                                      (float4*)d_out, nrows);
}

// round 5
// speedup vs baseline: 4.4541x; 1.1044x over previous
#include <cuda_runtime.h>
#include <cstdint>

#define NI 64

typedef unsigned long long u64;

__device__ __forceinline__ u64 pk2(float lo, float hi) {
    u64 r;
    asm("mov.b64 %0, {%1, %2};" : "=l"(r) : "f"(lo), "f"(hi));
    return r;
}
__device__ __forceinline__ void upk2(u64 v, float& lo, float& hi) {
    asm("mov.b64 {%0, %1}, %2;" : "=f"(lo), "=f"(hi) : "l"(v));
}
__device__ __forceinline__ u64 fma2(u64 a, u64 b, u64 c) {
    u64 d;
    asm("fma.rn.f32x2 %0, %1, %2, %3;" : "=l"(d) : "l"(a), "l"(b), "l"(c));
    return d;
}
__device__ __forceinline__ u64 add2(u64 a, u64 b) {
    u64 d;
    asm("add.rn.f32x2 %0, %1, %2;" : "=l"(d) : "l"(a), "l"(b));
    return d;
}
// f32x2 -> f16x2 -> tanh -> f32x2  (1 MUFU for a packed pair)
__device__ __forceinline__ u64 tanh_pair(u64 pa) {
    float lo, hi;
    upk2(pa, lo, hi);
    unsigned h;
    asm("cvt.rn.f16x2.f32 %0, %1, %2;" : "=r"(h) : "f"(hi), "f"(lo)); // lo in bits[15:0]
    asm("tanh.approx.f16x2 %0, %0;" : "+r"(h));
    float tlo, thi;
    asm("{ .reg .b16 l, u;\n\t"
        "  mov.b32 {l, u}, %2;\n\t"
        "  cvt.f32.f16 %0, l;\n\t"
        "  cvt.f32.f16 %1, u; }"
        : "=f"(tlo), "=f"(thi) : "r"(h));
    return pk2(tlo, thi);
}

// Shared constants, duplicated for packed f32x2 broadcast:
//   wA[i] = {w0,w0, w1,w1}
//   wB[i] = {b,b,   c0,c0}   c0 = W_out[i]*W_in[0][i]
//   wC[i] = {c1,c1}          c1 = W_out[i]*W_in[1][i]
__global__ __launch_bounds__(256, 3) void henon_kernel(
    const float4* __restrict__ z,
    const float*  __restrict__ W_in,
    const float*  __restrict__ W_out,
    const float*  __restrict__ b_in,
    const float*  __restrict__ eta,
    float4* __restrict__ out,
    int nrows)
{
    __shared__ float4 wA[NI];
    __shared__ float4 wB[NI];
    __shared__ float2 wC[NI];

    int t = threadIdx.x;
    if (t < NI) {
        float w0 = W_in[t];
        float w1 = W_in[NI + t];
        float wo = W_out[t];
        float b  = b_in[t];
        wA[t] = make_float4(w0, w0, w1, w1);
        wB[t] = make_float4(b, b, wo * w0, wo * w0);
        wC[t] = make_float2(wo * w1, wo * w1);
    }
    float e0 = __ldg(&eta[0]);
    float e1 = __ldg(&eta[1]);
    __syncthreads();

    int q = (nrows + 3) >> 2;           // rows per quarter
    int idx = blockIdx.x * blockDim.x + t;
    if (idx >= q) return;

    int i1 = idx + q;
    int i2 = idx + 2 * q;
    int i3 = idx + 3 * q;
    bool h1v = i1 < nrows, h2v = i2 < nrows, h3v = i3 < nrows;
    int i1c = h1v ? i1 : idx;
    int i2c = h2v ? i2 : idx;
    int i3c = h3v ? i3 : idx;

    float4 z0 = z[idx];
    float4 z1 = z[i1c];
    float4 z2 = z[i2c];
    float4 z3 = z[i3c];

    // Pair A = rows (idx, i1), pair B = rows (i2, i3). lo=first row.
    u64 aX0 = pk2(z0.x, z1.x), aX1 = pk2(z0.y, z1.y);
    u64 aY0 = pk2(z0.z, z1.z), aY1 = pk2(z0.w, z1.w);
    u64 bX0 = pk2(z2.x, z3.x), bX1 = pk2(z2.y, z3.y);
    u64 bY0 = pk2(z2.z, z3.z), bY1 = pk2(z2.w, z3.w);

    const u64 negone2 = pk2(-1.0f, -1.0f);
    const u64 pe0 = pk2(e0, e0);
    const u64 pe1 = pk2(e1, e1);
    const u64 SGN = 0x8000000080000000ull;

    const ulonglong2* wA64 = (const ulonglong2*)wA;
    const ulonglong2* wB64 = (const ulonglong2*)wB;
    const u64*        wC64 = (const u64*)wC;

    #pragma unroll 1
    for (int it = 0; it < 4; ++it) {
        // h = sum (t^2 - 1) * c  ==  -grad
        u64 ah0 = 0ull, ah1 = 0ull, bh0 = 0ull, bh1 = 0ull;
        #pragma unroll 4
        for (int i = 0; i < NI; ++i) {
            ulonglong2 a4 = wA64[i];      // {w0,w0},{w1,w1}
            ulonglong2 b4 = wB64[i];      // {b,b},{c0,c0}
            u64 c2        = wC64[i];      // {c1,c1}

            u64 paA = fma2(aY0, a4.x, fma2(aY1, a4.y, b4.x));
            u64 tA  = tanh_pair(paA);
            u64 uA  = fma2(tA, tA, negone2);        // t^2 - 1
            ah0 = fma2(uA, b4.y, ah0);
            ah1 = fma2(uA, c2,   ah1);

            u64 paB = fma2(bY0, a4.x, fma2(bY1, a4.y, b4.x));
            u64 tB  = tanh_pair(paB);
            u64 uB  = fma2(tB, tB, negone2);
            bh0 = fma2(uB, b4.y, bh0);
            bh1 = fma2(uB, c2,   bh1);
        }
        // X' = Y + eta ; Y' = -X + grad = -(X + h)
        u64 naX0 = add2(aY0, pe0);
        u64 naX1 = add2(aY1, pe1);
        u64 naY0 = add2(aX0, ah0) ^ SGN;
        u64 naY1 = add2(aX1, ah1) ^ SGN;
        aX0 = naX0; aX1 = naX1; aY0 = naY0; aY1 = naY1;

        u64 nbX0 = add2(bY0, pe0);
        u64 nbX1 = add2(bY1, pe1);
        u64 nbY0 = add2(bX0, bh0) ^ SGN;
        u64 nbY1 = add2(bX1, bh1) ^ SGN;
        bX0 = nbX0; bX1 = nbX1; bY0 = nbY0; bY1 = nbY1;
    }

    float r0x, r1x, r0y, r1y, r0z, r1z, r0w, r1w;
    upk2(aX0, r0x, r1x); upk2(aX1, r0y, r1y);
    upk2(aY0, r0z, r1z); upk2(aY1, r0w, r1w);
    out[idx] = make_float4(r0x, r0y, r0z, r0w);
    if (h1v) out[i1] = make_float4(r1x, r1y, r1z, r1w);

    upk2(bX0, r0x, r1x); upk2(bX1, r0y, r1y);
    upk2(bY0, r0z, r1z); upk2(bY1, r0w, r1w);
    if (h2v) out[i2] = make_float4(r0x, r0y, r0z, r0w);
    if (h3v) out[i3] = make_float4(r1x, r1y, r1z, r1w);
}

extern "C" void kernel_launch(void* const* d_in, const int* in_sizes, int n_in,
                              void* d_out, int out_size)
{
    const float4* z     = (const float4*)d_in[0];
    const float*  W_in  = (const float*)d_in[1];
    const float*  W_out = (const float*)d_in[2];
    const float*  b_in  = (const float*)d_in[3];
    const float*  eta   = (const float*)d_in[4];
    int nrows = in_sizes[0] / 4;
    int q = (nrows + 3) / 4;

    int threads = 256;
    int blocks = (q + threads - 1) / threads;
    henon_kernel<<<blocks, threads>>>(z, W_in, W_out, b_in, eta,
                                      (float4*)d_out, nrows);
}

// round 6
// speedup vs baseline: 4.8239x; 1.0830x over previous
#include <cuda_runtime.h>
#include <cstdint>

#define NI 64

typedef unsigned long long u64;
typedef unsigned int u32;

__device__ __forceinline__ u64 pk2(float lo, float hi) {
    u64 r;
    asm("mov.b64 %0, {%1, %2};" : "=l"(r) : "f"(lo), "f"(hi));
    return r;
}
__device__ __forceinline__ void upk2(u64 v, float& lo, float& hi) {
    asm("mov.b64 {%0, %1}, %2;" : "=f"(lo), "=f"(hi) : "l"(v));
}
__device__ __forceinline__ u64 fma2(u64 a, u64 b, u64 c) {
    u64 d;
    asm("fma.rn.f32x2 %0, %1, %2, %3;" : "=l"(d) : "l"(a), "l"(b), "l"(c));
    return d;
}
__device__ __forceinline__ u64 add2(u64 a, u64 b) {
    u64 d;
    asm("add.rn.f32x2 %0, %1, %2;" : "=l"(d) : "l"(a), "l"(b));
    return d;
}
// pack two f32 -> f16x2 (hi -> bits[31:16], lo -> bits[15:0])
__device__ __forceinline__ u32 pack_h2(u64 pa) {
    float lo, hi;
    upk2(pa, lo, hi);
    u32 h;
    asm("cvt.rn.f16x2.f32 %0, %1, %2;" : "=r"(h) : "f"(hi), "f"(lo));
    return h;
}
__device__ __forceinline__ u32 tanh_h2(u32 h) {
    asm("tanh.approx.f16x2 %0, %0;" : "+r"(h));
    return h;
}
__device__ __forceinline__ u32 hfma2(u32 a, u32 b, u32 c) {
    u32 d;
    asm("fma.rn.f16x2 %0, %1, %2, %3;" : "=r"(d) : "r"(a), "r"(b), "r"(c));
    return d;
}
// f16x2 -> packed f32x2 (lane order preserved)
__device__ __forceinline__ u64 h2_to_f32x2(u32 h) {
    float lo, hi;
    asm("{ .reg .b16 l, u;\n\t"
        "  mov.b32 {l, u}, %2;\n\t"
        "  cvt.f32.f16 %0, l;\n\t"
        "  cvt.f32.f16 %1, u; }"
        : "=f"(lo), "=f"(hi) : "r"(h));
    return pk2(lo, hi);
}

// Shared constants per neuron (2 x LDS.128):
//   wA[i] = {w0,w0, w1,w1}                       (f32 duplicated pairs)
//   wB[i] = {b,b, bits(c0c0_f16x2), bits(c1c1_f16x2)}
// where c0 = W_out[i]*W_in[0][i], c1 = W_out[i]*W_in[1][i]
__global__ __launch_bounds__(256, 4) void henon_kernel(
    const float4* __restrict__ z,
    const float*  __restrict__ W_in,
    const float*  __restrict__ W_out,
    const float*  __restrict__ b_in,
    const float*  __restrict__ eta,
    float4* __restrict__ out,
    int nrows)
{
    __shared__ float4 wA[NI];
    __shared__ uint4  wB[NI];

    int t = threadIdx.x;
    if (t < NI) {
        float w0 = W_in[t];
        float w1 = W_in[NI + t];
        float wo = W_out[t];
        float b  = b_in[t];
        float c0 = wo * w0;
        float c1 = wo * w1;
        u32 c0h, c1h;
        asm("cvt.rn.f16x2.f32 %0, %1, %1;" : "=r"(c0h) : "f"(c0));
        asm("cvt.rn.f16x2.f32 %0, %1, %1;" : "=r"(c1h) : "f"(c1));
        wA[t] = make_float4(w0, w0, w1, w1);
        wB[t] = make_uint4(__float_as_uint(b), __float_as_uint(b), c0h, c1h);
    }
    float e0 = __ldg(&eta[0]);
    float e1 = __ldg(&eta[1]);
    __syncthreads();

    int q = (nrows + 3) >> 2;
    int idx = blockIdx.x * blockDim.x + t;
    if (idx >= q) return;

    int i1 = idx + q;
    int i2 = idx + 2 * q;
    int i3 = idx + 3 * q;
    bool h1v = i1 < nrows, h2v = i2 < nrows, h3v = i3 < nrows;
    int i1c = h1v ? i1 : idx;
    int i2c = h2v ? i2 : idx;
    int i3c = h3v ? i3 : idx;

    float4 z0 = z[idx];
    float4 z1 = z[i1c];
    float4 z2 = z[i2c];
    float4 z3 = z[i3c];

    // Pair A = rows (idx,i1), pair B = rows (i2,i3). lo = first row.
    u64 aX0 = pk2(z0.x, z1.x), aX1 = pk2(z0.y, z1.y);
    u64 aY0 = pk2(z0.z, z1.z), aY1 = pk2(z0.w, z1.w);
    u64 bX0 = pk2(z2.x, z3.x), bX1 = pk2(z2.y, z3.y);
    u64 bY0 = pk2(z2.z, z3.z), bY1 = pk2(z2.w, z3.w);

    const u64 pe0 = pk2(e0, e0);
    const u64 pe1 = pk2(e1, e1);
    const u64 SGN = 0x8000000080000000ull;
    const u32 NEG1H = 0xBC00BC00u;   // f16x2 {-1,-1}

    const ulonglong2* wA64 = (const ulonglong2*)wA;
    const ulonglong2* wB64 = (const ulonglong2*)wB;

    #pragma unroll 1
    for (int it = 0; it < 4; ++it) {
        // G = sum (t^2-1)*c in f32x2 (== -grad); chunked f16x2 partials.
        u64 Ga0 = 0ull, Ga1 = 0ull, Gb0 = 0ull, Gb1 = 0ull;

        #pragma unroll 1
        for (int ch = 0; ch < 4; ++ch) {
            u32 ha0 = 0u, ha1 = 0u, hb0 = 0u, hb1 = 0u;
            int base = ch * 16;
            #pragma unroll 2
            for (int j = 0; j < 16; ++j) {
                int i = base + j;
                ulonglong2 a4 = wA64[i];           // {w0,w0},{w1,w1}
                ulonglong2 b4 = wB64[i];           // {b,b}, {c0h2, c1h2}
                u32 c0h = (u32)(b4.y & 0xffffffffull);
                u32 c1h = (u32)(b4.y >> 32);

                u64 paA = fma2(aY0, a4.x, fma2(aY1, a4.y, b4.x));
                u32 tA  = tanh_h2(pack_h2(paA));
                u32 uA  = hfma2(tA, tA, NEG1H);    // t^2 - 1
                ha0 = hfma2(uA, c0h, ha0);
                ha1 = hfma2(uA, c1h, ha1);

                u64 paB = fma2(bY0, a4.x, fma2(bY1, a4.y, b4.x));
                u32 tB  = tanh_h2(pack_h2(paB));
                u32 uB  = hfma2(tB, tB, NEG1H);
                hb0 = hfma2(uB, c0h, hb0);
                hb1 = hfma2(uB, c1h, hb1);
            }
            Ga0 = add2(Ga0, h2_to_f32x2(ha0));
            Ga1 = add2(Ga1, h2_to_f32x2(ha1));
            Gb0 = add2(Gb0, h2_to_f32x2(hb0));
            Gb1 = add2(Gb1, h2_to_f32x2(hb1));
        }

        // X' = Y + eta ; Y' = -X + grad = -(X + G)
        u64 naX0 = add2(aY0, pe0);
        u64 naX1 = add2(aY1, pe1);
        u64 naY0 = add2(aX0, Ga0) ^ SGN;
        u64 naY1 = add2(aX1, Ga1) ^ SGN;
        aX0 = naX0; aX1 = naX1; aY0 = naY0; aY1 = naY1;

        u64 nbX0 = add2(bY0, pe0);
        u64 nbX1 = add2(bY1, pe1);
        u64 nbY0 = add2(bX0, Gb0) ^ SGN;
        u64 nbY1 = add2(bX1, Gb1) ^ SGN;
        bX0 = nbX0; bX1 = nbX1; bY0 = nbY0; bY1 = nbY1;
    }

    float r0x, r1x, r0y, r1y, r0z, r1z, r0w, r1w;
    upk2(aX0, r0x, r1x); upk2(aX1, r0y, r1y);
    upk2(aY0, r0z, r1z); upk2(aY1, r0w, r1w);
    out[idx] = make_float4(r0x, r0y, r0z, r0w);
    if (h1v) out[i1] = make_float4(r1x, r1y, r1z, r1w);

    upk2(bX0, r0x, r1x); upk2(bX1, r0y, r1y);
    upk2(bY0, r0z, r1z); upk2(bY1, r0w, r1w);
    if (h2v) out[i2] = make_float4(r0x, r0y, r0z, r0w);
    if (h3v) out[i3] = make_float4(r1x, r1y, r1z, r1w);
}

extern "C" void kernel_launch(void* const* d_in, const int* in_sizes, int n_in,
                              void* d_out, int out_size)
{
    const float4* z     = (const float4*)d_in[0];
    const float*  W_in  = (const float*)d_in[1];
    const float*  W_out = (const float*)d_in[2];
    const float*  b_in  = (const float*)d_in[3];
    const float*  eta   = (const float*)d_in[4];
    int nrows = in_sizes[0] / 4;
    int q = (nrows + 3) / 4;

    int threads = 256;
    int blocks = (q + threads - 1) / threads;
    henon_kernel<<<blocks, threads>>>(z, W_in, W_out, b_in, eta,
                                      (float4*)d_out, nrows);
}